// round 12
// baseline (speedup 1.0000x reference)
#include <cuda_runtime.h>
#include <math.h>

#define SCALE 64.0f
#define MARGIN 0.35f
#define TPB 256
#define GROUPS 4                  // float4 groups per thread -> 16 elem/thread
#define TILE (TPB * GROUPS * 4)   // 4096 output elements per block

// Output layout (f32, flattened tuple in reference order):
//   [0, B*(C-1))            diff_logits, row-major
//   [B*(C-1), +B)           sin_theta
//   [+B, +2B)               sin_theta_plus_m
//   [+2B, +3B)              sin_m
//
// Labels dtype sniff: for LE int64 labels in [0, 100000) every odd 32-bit
// word is 0; for int32 labels those words are random. 8 odd words decide.
__device__ __forceinline__ bool labels_are_i64(const int* labels32) {
    bool is_i64 = true;
#pragma unroll
    for (int k = 1; k <= 15; k += 2) is_i64 &= (labels32[k] == 0);
    return is_i64;
}

__global__ void __launch_bounds__(TPB, 8)
cosface_kernel(const float* __restrict__ logits,
               const int* __restrict__ labels32,
               float* __restrict__ out,
               int B, int C) {
    const int Cm1 = C - 1;
    const bool i64 = labels_are_i64(labels32);
    const int total = B * Cm1;
    const int total4 = total >> 2;

    const int tb = blockIdx.x * TILE;
    const int r0 = tb / Cm1;                       // one division per block
    const int base0 = r0 * Cm1;
    const int b1 = base0 + Cm1;
    const int lab0 = i64 ? labels32[2 * r0] : labels32[r0];
    const size_t lbase0 = (size_t)r0 * (size_t)C;
    const float ft0 = __ldg(logits + lbase0 + lab0) - MARGIN;

    const int j0 = tb - base0;                     // block's first j in row r0
    float4* __restrict__ out4 = reinterpret_cast<float4*>(out);

    const bool uniform = (tb + TILE <= b1) && (tb + TILE <= total) &&
                         (lab0 <= j0 || lab0 >= j0 + TILE);

    if (uniform) {
        // FAST PATH (~68% of blocks): single row, constant column shift.
        // Two phases of (8 batched loads -> 2 aligned st.128) to fit 32 regs.
        const int shift = (j0 >= lab0) ? 1 : 0;
        const float* __restrict__ p = logits + lbase0 + j0 + shift;
        float4* __restrict__ o4 = out4 + (tb >> 2);

#pragma unroll
        for (int ph = 0; ph < 2; ph++) {
            float v[2][4];
#pragma unroll
            for (int g = 0; g < 2; g++) {
                const int e0 = (threadIdx.x + (ph * 2 + g) * TPB) << 2;
#pragma unroll
                for (int e = 0; e < 4; e++) v[g][e] = __ldcs(p + e0 + e);
            }
#pragma unroll
            for (int g = 0; g < 2; g++) {
                float4 o;
                o.x = SCALE * (v[g][0] - ft0);
                o.y = SCALE * (v[g][1] - ft0);
                o.z = SCALE * (v[g][2] - ft0);
                o.w = SCALE * (v[g][3] - ft0);
                __stcs(o4 + threadIdx.x + (ph * 2 + g) * TPB, o);
            }
        }
    } else {
        // SLOW PATH: block contains the label and/or crosses a row boundary.
        const int r1 = (r0 + 1 < B) ? r0 + 1 : r0;
        const int lab1 = i64 ? labels32[2 * r1] : labels32[r1];
        const size_t lbase1 = (size_t)r1 * (size_t)C;
        const float ft1 = __ldg(logits + lbase1 + lab1) - MARGIN;

#pragma unroll
        for (int ph = 0; ph < 2; ph++) {
            float v[2][4];
            int idx4[2];
            bool ok[2];
#pragma unroll
            for (int g = 0; g < 2; g++) {
                idx4[g] = (tb >> 2) + threadIdx.x + (ph * 2 + g) * TPB;
                ok[g] = (idx4[g] < total4);
                if (ok[g]) {
                    const int t0 = idx4[g] << 2;
#pragma unroll
                    for (int e = 0; e < 4; e++) {
                        const int t = t0 + e;
                        const bool hi = (t >= b1);
                        const int j = t - (hi ? b1 : base0);
                        const int lab = hi ? lab1 : lab0;
                        const size_t src = (hi ? lbase1 : lbase0) + j + (j >= lab);
                        v[g][e] = __ldcs(logits + src);
                    }
                }
            }
#pragma unroll
            for (int g = 0; g < 2; g++) {
                if (ok[g]) {
                    const int t0 = idx4[g] << 2;
                    float4 o;
                    o.x = SCALE * (v[g][0] - ((t0 + 0 >= b1) ? ft1 : ft0));
                    o.y = SCALE * (v[g][1] - ((t0 + 1 >= b1) ? ft1 : ft0));
                    o.z = SCALE * (v[g][2] - ((t0 + 2 >= b1) ? ft1 : ft0));
                    o.w = SCALE * (v[g][3] - ((t0 + 3 >= b1) ? ft1 : ft0));
                    __stcs(out4 + idx4[g], o);
                }
            }
        }
    }

    // Epilogue scalars: block 0 computes all B rows' sines.
    if (blockIdx.x == 0) {
        const size_t sbase = (size_t)B * (size_t)Cm1;
        for (int r = threadIdx.x; r < B; r += TPB) {
            const int lab = i64 ? labels32[2 * r] : labels32[r];
            const float tg = __ldg(logits + (size_t)r * (size_t)C + lab);
            const float ftv = tg - MARGIN;
            // sin(acos(x)) == sqrt(1 - x^2) on [0,1)
            out[sbase + r]          = sqrtf(fmaxf(0.0f, 1.0f - tg * tg));
            out[sbase + B + r]      = sqrtf(fmaxf(0.0f, 1.0f - ftv * ftv));
            out[sbase + 2 * B + r]  = sinf(acosf(ftv) - acosf(tg));
        }
    }
}

extern "C" void kernel_launch(void* const* d_in, const int* in_sizes, int n_in,
                              void* d_out, int out_size) {
    const float* logits = (const float*)d_in[0];
    const int* labels32 = (const int*)d_in[1];
    float* out = (float*)d_out;

    const int B = in_sizes[1];              // 512
    const int C = in_sizes[0] / B;          // 100000

    const long long total = (long long)B * (C - 1);
    const int nblocks = (int)((total + TILE - 1) / TILE);   // 12500
    cosface_kernel<<<nblocks, TPB>>>(logits, labels32, out, B, C);
}

// round 13
// speedup vs baseline: 1.0005x; 1.0005x over previous
#include <cuda_runtime.h>
#include <math.h>

#define SCALE 64.0f
#define MARGIN 0.35f
#define TPB 256
#define GROUPS 4                  // float4 groups per thread -> 16 elem/thread
#define TILE (TPB * GROUPS * 4)   // 4096 output elements per block

// Output layout (f32, flattened tuple in reference order):
//   [0, B*(C-1))            diff_logits, row-major
//   [B*(C-1), +B)           sin_theta
//   [+B, +2B)               sin_theta_plus_m
//   [+2B, +3B)              sin_m
//
// Labels dtype sniff: for LE int64 labels in [0, 100000) every odd 32-bit
// word is 0; for int32 labels those words are random. 8 odd words decide.
__device__ __forceinline__ bool labels_are_i64(const int* labels32) {
    bool is_i64 = true;
#pragma unroll
    for (int k = 1; k <= 15; k += 2) is_i64 &= (labels32[k] == 0);
    return is_i64;
}

__global__ void __launch_bounds__(TPB, 8)
cosface_kernel(const float* __restrict__ logits,
               const int* __restrict__ labels32,
               float* __restrict__ out,
               int B, int C) {
    const int Cm1 = C - 1;
    const bool i64 = labels_are_i64(labels32);
    const int total = B * Cm1;
    const int total4 = total >> 2;

    const int tb = blockIdx.x * TILE;
    const int r0 = tb / Cm1;                       // one division per block
    const int base0 = r0 * Cm1;
    const int b1 = base0 + Cm1;
    const int lab0 = i64 ? labels32[2 * r0] : labels32[r0];
    const size_t lbase0 = (size_t)r0 * (size_t)C;
    const float ft0 = __ldg(logits + lbase0 + lab0) - MARGIN;

    const int j0 = tb - base0;                     // block's first j in row r0
    float4* __restrict__ out4 = reinterpret_cast<float4*>(out);

    const bool uniform = (tb + TILE <= b1) && (tb + TILE <= total) &&
                         (lab0 <= j0 || lab0 >= j0 + TILE);

    if (uniform) {
        // FAST PATH (~68% of blocks): single row, constant column shift.
        // Two phases of (8 batched loads -> 2 aligned st.128) to fit 32 regs.
        const int shift = (j0 >= lab0) ? 1 : 0;
        const float* __restrict__ p = logits + lbase0 + j0 + shift;
        float4* __restrict__ o4 = out4 + (tb >> 2);

#pragma unroll
        for (int ph = 0; ph < 2; ph++) {
            float v[2][4];
#pragma unroll
            for (int g = 0; g < 2; g++) {
                const int e0 = (threadIdx.x + (ph * 2 + g) * TPB) << 2;
#pragma unroll
                for (int e = 0; e < 4; e++) v[g][e] = __ldcs(p + e0 + e);
            }
#pragma unroll
            for (int g = 0; g < 2; g++) {
                float4 o;
                o.x = SCALE * (v[g][0] - ft0);
                o.y = SCALE * (v[g][1] - ft0);
                o.z = SCALE * (v[g][2] - ft0);
                o.w = SCALE * (v[g][3] - ft0);
                __stcs(o4 + threadIdx.x + (ph * 2 + g) * TPB, o);
            }
        }
    } else {
        // SLOW PATH: block contains the label and/or crosses a row boundary.
        const int r1 = (r0 + 1 < B) ? r0 + 1 : r0;
        const int lab1 = i64 ? labels32[2 * r1] : labels32[r1];
        const size_t lbase1 = (size_t)r1 * (size_t)C;
        const float ft1 = __ldg(logits + lbase1 + lab1) - MARGIN;

#pragma unroll
        for (int ph = 0; ph < 2; ph++) {
            float v[2][4];
            int idx4[2];
            bool ok[2];
#pragma unroll
            for (int g = 0; g < 2; g++) {
                idx4[g] = (tb >> 2) + threadIdx.x + (ph * 2 + g) * TPB;
                ok[g] = (idx4[g] < total4);
                if (ok[g]) {
                    const int t0 = idx4[g] << 2;
#pragma unroll
                    for (int e = 0; e < 4; e++) {
                        const int t = t0 + e;
                        const bool hi = (t >= b1);
                        const int j = t - (hi ? b1 : base0);
                        const int lab = hi ? lab1 : lab0;
                        const size_t src = (hi ? lbase1 : lbase0) + j + (j >= lab);
                        v[g][e] = __ldcs(logits + src);
                    }
                }
            }
#pragma unroll
            for (int g = 0; g < 2; g++) {
                if (ok[g]) {
                    const int t0 = idx4[g] << 2;
                    float4 o;
                    o.x = SCALE * (v[g][0] - ((t0 + 0 >= b1) ? ft1 : ft0));
                    o.y = SCALE * (v[g][1] - ((t0 + 1 >= b1) ? ft1 : ft0));
                    o.z = SCALE * (v[g][2] - ((t0 + 2 >= b1) ? ft1 : ft0));
                    o.w = SCALE * (v[g][3] - ((t0 + 3 >= b1) ? ft1 : ft0));
                    __stcs(out4 + idx4[g], o);
                }
            }
        }
    }

    // Epilogue scalars: block 0 computes all B rows' sines.
    if (blockIdx.x == 0) {
        const size_t sbase = (size_t)B * (size_t)Cm1;
        for (int r = threadIdx.x; r < B; r += TPB) {
            const int lab = i64 ? labels32[2 * r] : labels32[r];
            const float tg = __ldg(logits + (size_t)r * (size_t)C + lab);
            const float ftv = tg - MARGIN;
            // sin(acos(x)) == sqrt(1 - x^2) on [0,1)
            out[sbase + r]          = sqrtf(fmaxf(0.0f, 1.0f - tg * tg));
            out[sbase + B + r]      = sqrtf(fmaxf(0.0f, 1.0f - ftv * ftv));
            out[sbase + 2 * B + r]  = sinf(acosf(ftv) - acosf(tg));
        }
    }
}

extern "C" void kernel_launch(void* const* d_in, const int* in_sizes, int n_in,
                              void* d_out, int out_size) {
    const float* logits = (const float*)d_in[0];
    const int* labels32 = (const int*)d_in[1];
    float* out = (float*)d_out;

    const int B = in_sizes[1];              // 512
    const int C = in_sizes[0] / B;          // 100000

    const long long total = (long long)B * (C - 1);
    const int nblocks = (int)((total + TILE - 1) / TILE);   // 12500
    cosface_kernel<<<nblocks, TPB>>>(logits, labels32, out, B, C);
}

// round 15
// speedup vs baseline: 1.0630x; 1.0625x over previous
#include <cuda_runtime.h>
#include <math.h>

#define SCALE 64.0f
#define MARGIN 0.35f
#define TPB 256
#define GROUPS 4                  // float4 groups per thread -> 16 elem/thread
#define TILE (TPB * GROUPS * 4)   // 4096 output elements per block

// Output layout (f32, flattened tuple in reference order):
//   [0, B*(C-1))            diff_logits, row-major
//   [B*(C-1), +B)           sin_theta
//   [+B, +2B)               sin_theta_plus_m
//   [+2B, +3B)              sin_m
//
// Labels dtype sniff: for LE int64 labels in [0, 100000) every odd 32-bit
// word is 0; for int32 labels those words are random. 8 odd words decide.
__device__ __forceinline__ bool labels_are_i64(const int* labels32) {
    bool is_i64 = true;
#pragma unroll
    for (int k = 1; k <= 15; k += 2) is_i64 &= (labels32[k] == 0);
    return is_i64;
}

__global__ void cosface_kernel(const float* __restrict__ logits,
                               const int* __restrict__ labels32,
                               float* __restrict__ out,
                               int B, int C) {
    const int Cm1 = C - 1;
    const bool i64 = labels_are_i64(labels32);
    const int total = B * Cm1;
    const int total4 = total >> 2;

    const int tb = blockIdx.x * TILE;
    const int r0 = tb / Cm1;                       // one division per block
    const int base0 = r0 * Cm1;
    const int b1 = base0 + Cm1;
    const int lab0 = i64 ? labels32[2 * r0] : labels32[r0];
    const size_t lbase0 = (size_t)r0 * (size_t)C;
    const float ft0 = __ldg(logits + lbase0 + lab0) - MARGIN;

    const int j0 = tb - base0;                     // block's first j in row r0
    float4* __restrict__ out4 = reinterpret_cast<float4*>(out);

    const int shift = (j0 >= lab0) ? 1 : 0;
    const size_t s = lbase0 + (size_t)j0 + shift;  // first src element
    const int off = (int)(s & 3);                  // uniform per block
    // Lane-31 helper load may touch up to 16B past the block's range; keep it
    // inside the logits array or fall back to the slow path.
    const bool tail_ok = (off == 0) ||
                         (s - off + (size_t)TILE + 4 <= (size_t)B * (size_t)C);

    const bool uniform = (tb + TILE <= b1) && (tb + TILE <= total) &&
                         (lab0 <= j0 || lab0 >= j0 + TILE) && tail_ok;

    if (uniform) {
        // FAST PATH: aligned LDG.128 + in-warp rotate by `off`, aligned ST.128.
        const float4* __restrict__ A =
            reinterpret_cast<const float4*>(logits + (s - off));
        float4* __restrict__ o4 = out4 + (tb >> 2);
        const int lane = threadIdx.x & 31;

        float4 a[GROUPS];
#pragma unroll
        for (int g = 0; g < GROUPS; g++)
            a[g] = __ldcs(A + threadIdx.x + g * TPB);

        float4 b[GROUPS];
        if (off != 0 && lane == 31) {
#pragma unroll
            for (int g = 0; g < GROUPS; g++)
                b[g] = __ldcs(A + threadIdx.x + g * TPB + 1);
        }

#pragma unroll
        for (int g = 0; g < GROUPS; g++) {
            float4 r;
            if (off == 0) {
                r = a[g];
            } else {
                float nx = __shfl_down_sync(0xFFFFFFFFu, a[g].x, 1);
                float ny = __shfl_down_sync(0xFFFFFFFFu, a[g].y, 1);
                float nz = __shfl_down_sync(0xFFFFFFFFu, a[g].z, 1);
                if (lane == 31) { nx = b[g].x; ny = b[g].y; nz = b[g].z; }
                if (off == 1)      r = make_float4(a[g].y, a[g].z, a[g].w, nx);
                else if (off == 2) r = make_float4(a[g].z, a[g].w, nx, ny);
                else               r = make_float4(a[g].w, nx, ny, nz);
            }
            float4 o;
            o.x = SCALE * (r.x - ft0);
            o.y = SCALE * (r.y - ft0);
            o.z = SCALE * (r.z - ft0);
            o.w = SCALE * (r.w - ft0);
            __stcs(o4 + threadIdx.x + g * TPB, o);
        }
    } else {
        // SLOW PATH: label inside block, row boundary, or array tail.
        const int r1 = (r0 + 1 < B) ? r0 + 1 : r0;
        const int lab1 = i64 ? labels32[2 * r1] : labels32[r1];
        const size_t lbase1 = (size_t)r1 * (size_t)C;
        const float ft1 = __ldg(logits + lbase1 + lab1) - MARGIN;

#pragma unroll
        for (int ph = 0; ph < 2; ph++) {
            float v[2][4];
            int idx4[2];
            bool ok[2];
#pragma unroll
            for (int g = 0; g < 2; g++) {
                idx4[g] = (tb >> 2) + threadIdx.x + (ph * 2 + g) * TPB;
                ok[g] = (idx4[g] < total4);
                if (ok[g]) {
                    const int t0 = idx4[g] << 2;
#pragma unroll
                    for (int e = 0; e < 4; e++) {
                        const int t = t0 + e;
                        const bool hi = (t >= b1);
                        const int j = t - (hi ? b1 : base0);
                        const int lab = hi ? lab1 : lab0;
                        const size_t src = (hi ? lbase1 : lbase0) + j + (j >= lab);
                        v[g][e] = __ldcs(logits + src);
                    }
                }
            }
#pragma unroll
            for (int g = 0; g < 2; g++) {
                if (ok[g]) {
                    const int t0 = idx4[g] << 2;
                    float4 o;
                    o.x = SCALE * (v[g][0] - ((t0 + 0 >= b1) ? ft1 : ft0));
                    o.y = SCALE * (v[g][1] - ((t0 + 1 >= b1) ? ft1 : ft0));
                    o.z = SCALE * (v[g][2] - ((t0 + 2 >= b1) ? ft1 : ft0));
                    o.w = SCALE * (v[g][3] - ((t0 + 3 >= b1) ? ft1 : ft0));
                    __stcs(out4 + idx4[g], o);
                }
            }
        }
    }

    // Epilogue scalars: block 0 computes all B rows' sines.
    if (blockIdx.x == 0) {
        const size_t sbase = (size_t)B * (size_t)Cm1;
        for (int r = threadIdx.x; r < B; r += TPB) {
            const int lab = i64 ? labels32[2 * r] : labels32[r];
            const float tg = __ldg(logits + (size_t)r * (size_t)C + lab);
            const float ftv = tg - MARGIN;
            // sin(acos(x)) == sqrt(1 - x^2) on [0,1)
            out[sbase + r]          = sqrtf(fmaxf(0.0f, 1.0f - tg * tg));
            out[sbase + B + r]      = sqrtf(fmaxf(0.0f, 1.0f - ftv * ftv));
            out[sbase + 2 * B + r]  = sinf(acosf(ftv) - acosf(tg));
        }
    }
}

extern "C" void kernel_launch(void* const* d_in, const int* in_sizes, int n_in,
                              void* d_out, int out_size) {
    const float* logits = (const float*)d_in[0];
    const int* labels32 = (const int*)d_in[1];
    float* out = (float*)d_out;

    const int B = in_sizes[1];              // 512
    const int C = in_sizes[0] / B;          // 100000

    const long long total = (long long)B * (C - 1);
    const int nblocks = (int)((total + TILE - 1) / TILE);   // 12500
    cosface_kernel<<<nblocks, TPB>>>(logits, labels32, out, B, C);
}